// round 9
// baseline (speedup 1.0000x reference)
#include <cuda_runtime.h>

#define FDIM 128
#define KH 5
#define NMAX 100000
#define BN_EPS 1e-5f

typedef unsigned long long u64;

// ---------------- device scratch (static, no allocs) ----------------
__device__ float g_h[(size_t)NMAX * FDIM];   // agg  (51.2 MB)
__device__ float g_y[(size_t)NMAX * FDIM];   // y1   (51.2 MB)
__device__ float g_hopw[8];
__device__ float g_st1[256];                 // [0:128) colsum, [128:256) colsumsq
__device__ float g_st2[256];
__device__ float g_a1[FDIM], g_c1[FDIM];     // BN1 fused scale/shift
__device__ float g_a2[FDIM], g_c2[FDIM];     // BN2 fused scale/shift

// ---------------- f32x2 helpers ----------------
__device__ __forceinline__ u64 pk2(float lo, float hi) {
    u64 r;
    asm("mov.b64 %0, {%1, %2};" : "=l"(r) : "f"(lo), "f"(hi));
    return r;
}
__device__ __forceinline__ float2 upk2(u64 v) {
    float2 r;
    asm("mov.b64 {%0, %1}, %2;" : "=f"(r.x), "=f"(r.y) : "l"(v));
    return r;
}
#define FMA2(d, a, b) asm("fma.rn.f32x2 %0, %1, %2, %0;" : "+l"(d) : "l"(a), "l"(b))

// ---------------- softmax + zero stats ----------------
__global__ void k_prep(const float* __restrict__ hop_coef) {
    int t = threadIdx.x;
    if (t < 256) { g_st1[t] = 0.f; g_st2[t] = 0.f; }
    if (t == 0) {
        float v[KH];
        float m = -1e30f;
        for (int i = 0; i < KH; i++) { v[i] = hop_coef[i]; m = fmaxf(m, v[i]); }
        float s = 0.f;
        for (int i = 0; i < KH; i++) { v[i] = expf(v[i] - m); s += v[i]; }
        float inv = 1.f / s;
        for (int i = 0; i < KH; i++) g_hopw[i] = v[i] * inv;
    }
}

// ---------------- zero g_h ----------------
__global__ void k_zero_h(int n4) {
    float4 z = make_float4(0.f, 0.f, 0.f, 0.f);
    float4* h4 = (float4*)g_h;
    for (int i = blockIdx.x * blockDim.x + threadIdx.x; i < n4;
         i += gridDim.x * blockDim.x)
        h4[i] = z;
}

// ---------------- scatter-add: warp handles 32 edges, meta de-duplicated (R6 winner) ----------------
__global__ void k_scatter(const float* __restrict__ x,
                          const int* __restrict__ ei,
                          const int* __restrict__ ew, int E) {
    int lane = threadIdx.x & 31;
    int warp = (blockIdx.x * blockDim.x + threadIdx.x) >> 5;
    int base = warp * 32;
    if (base >= E) return;

    // lane e-th edge meta (coalesced)
    int e = base + lane;
    u64 mpack = 0;
    float wgt = 0.f;
    if (e < E) {
        int d = ew[e];
        if (d >= 1 && d <= KH) {
            wgt = g_hopw[d - 1];
            int r = ei[e];        // row
            int c = ei[E + e];    // col
            mpack = ((u64)(unsigned)r << 32) | (unsigned)c;
        }
    }

    #pragma unroll 4
    for (int j = 0; j < 32; j++) {
        float w = __shfl_sync(0xffffffffu, wgt, j);   // uniform across warp
        if (w == 0.f) continue;
        u64 m = __shfl_sync(0xffffffffu, mpack, j);
        int c = (int)(unsigned)m;
        int r = (int)(unsigned)(m >> 32);
        float4 v = ((const float4*)x)[(size_t)c * 32 + lane];
        v.x *= w; v.y *= w; v.z *= w; v.w *= w;
        atomicAdd(((float4*)g_h) + (size_t)r * 32 + lane, v);   // RED.128
    }
}

// ---------------- GEMM + fused BN-stats epilogue ----------------
// PHASE 1: A = g_h + x (GIN self term fused at stage), Y = g_y, stats -> g_st1
// PHASE 2: A = relu(a1*g_y + c1), Y = OutY, stats -> g_st2
// A tile stored TRANSPOSED At[k][r]; mainloop reads 4 row-pairs with
// TWO broadcast LDS.128 (was 4x LDS.64) -> 6 smem wavefronts/k vs FMA's 8.
// 256 threads: (tr=tid>>5, tc=tid&31) -> rows tr*8..+7, cols tc*4..+3.
template <int PHASE>
__global__ void __launch_bounds__(256) k_gemm(const float4* __restrict__ X,
                                              const float* __restrict__ W,
                                              float* __restrict__ OutY, int n) {
    const float* A = (PHASE == 1) ? g_h : g_y;
    float* Y       = (PHASE == 1) ? g_y : OutY;

    __shared__ __align__(16) float Ws[FDIM * 128];   // [k][c]  64 KB
    __shared__ __align__(16) float At[FDIM * 64];    // [k][r]  32 KB (transposed)
    __shared__ float sh_st[256];

    int tid = threadIdx.x;
    int tc = tid & 31, tr = tid >> 5;
    sh_st[tid] = 0.f;

    // stage W (coalesced, row-major [k][c])
    const float4* W4 = (const float4*)W;
    float4* Ws4 = (float4*)Ws;
    #pragma unroll 4
    for (int i = tid; i < FDIM * 32; i += 256) Ws4[i] = W4[i];

    // stage A transposed: i -> (c4 = i>>6, r = i&63); within a warp lanes span r
    // => STS banks = r%32 conflict-free; LDG 512B-strided but sector-complete.
    int row0 = blockIdx.x * 64;
    const float4* A4 = (const float4*)A;
    #pragma unroll
    for (int i = tid; i < 2048; i += 256) {
        int c4 = i >> 6, r = i & 63;
        float4 v = make_float4(0.f, 0.f, 0.f, 0.f);
        if (row0 + r < n) {
            v = A4[(size_t)(row0 + r) * 32 + c4];
            if (PHASE == 1) {
                float4 xv = X[(size_t)(row0 + r) * 32 + c4];
                v.x += xv.x; v.y += xv.y; v.z += xv.z; v.w += xv.w;
            } else {
                float4 a = __ldg(&((const float4*)g_a1)[c4]);
                float4 b = __ldg(&((const float4*)g_c1)[c4]);
                v.x = fmaxf(fmaf(a.x, v.x, b.x), 0.f);
                v.y = fmaxf(fmaf(a.y, v.y, b.y), 0.f);
                v.z = fmaxf(fmaf(a.z, v.z, b.z), 0.f);
                v.w = fmaxf(fmaf(a.w, v.w, b.w), 0.f);
            }
        }
        int k0 = c4 * 4;
        At[(k0 + 0) * 64 + r] = v.x;
        At[(k0 + 1) * 64 + r] = v.y;
        At[(k0 + 2) * 64 + r] = v.z;
        At[(k0 + 3) * 64 + r] = v.w;
    }
    __syncthreads();

    u64 acc[4][4];
    #pragma unroll
    for (int p = 0; p < 4; p++)
        #pragma unroll
        for (int c = 0; c < 4; c++) acc[p][c] = 0ULL;

    int r0 = tr * 8;
    #pragma unroll 4
    for (int k = 0; k < FDIM; k++) {
        float4 wv = Ws4[k * 32 + tc];                       // LDS.128, 4 wf
        u64 w0 = pk2(wv.x, wv.x);
        u64 w1 = pk2(wv.y, wv.y);
        u64 w2 = pk2(wv.z, wv.z);
        u64 w3 = pk2(wv.w, wv.w);
        // 2x broadcast LDS.128: 4 row-pairs (8 contiguous floats), 2 wf
        const ulonglong2* ak = (const ulonglong2*)&At[k * 64 + r0];
        ulonglong2 q01 = ak[0];
        ulonglong2 q23 = ak[1];
        u64 a0 = q01.x, a1 = q01.y, a2 = q23.x, a3 = q23.y;
        FMA2(acc[0][0], a0, w0); FMA2(acc[0][1], a0, w1);
        FMA2(acc[0][2], a0, w2); FMA2(acc[0][3], a0, w3);
        FMA2(acc[1][0], a1, w0); FMA2(acc[1][1], a1, w1);
        FMA2(acc[1][2], a1, w2); FMA2(acc[1][3], a1, w3);
        FMA2(acc[2][0], a2, w0); FMA2(acc[2][1], a2, w1);
        FMA2(acc[2][2], a2, w2); FMA2(acc[2][3], a2, w3);
        FMA2(acc[3][0], a3, w0); FMA2(acc[3][1], a3, w1);
        FMA2(acc[3][2], a3, w2); FMA2(acc[3][3], a3, w3);
    }

    // epilogue: store Y + per-column stats
    float cs[4] = {0.f, 0.f, 0.f, 0.f};
    float cq[4] = {0.f, 0.f, 0.f, 0.f};
    #pragma unroll
    for (int p = 0; p < 4; p++) {
        float2 c0 = upk2(acc[p][0]);
        float2 c1 = upk2(acc[p][1]);
        float2 c2 = upk2(acc[p][2]);
        float2 c3 = upk2(acc[p][3]);
        int r_lo = row0 + r0 + 2 * p;
        int r_hi = r_lo + 1;
        if (r_lo < n) {
            float4 o = make_float4(c0.x, c1.x, c2.x, c3.x);
            ((float4*)Y)[(size_t)r_lo * 32 + tc] = o;
            cs[0] += o.x; cs[1] += o.y; cs[2] += o.z; cs[3] += o.w;
            cq[0] += o.x * o.x; cq[1] += o.y * o.y;
            cq[2] += o.z * o.z; cq[3] += o.w * o.w;
        }
        if (r_hi < n) {
            float4 o = make_float4(c0.y, c1.y, c2.y, c3.y);
            ((float4*)Y)[(size_t)r_hi * 32 + tc] = o;
            cs[0] += o.x; cs[1] += o.y; cs[2] += o.z; cs[3] += o.w;
            cq[0] += o.x * o.x; cq[1] += o.y * o.y;
            cq[2] += o.z * o.z; cq[3] += o.w * o.w;
        }
    }
    #pragma unroll
    for (int c = 0; c < 4; c++) {
        atomicAdd(&sh_st[tc * 4 + c], cs[c]);
        atomicAdd(&sh_st[128 + tc * 4 + c], cq[c]);
    }
    __syncthreads();
    float* gst = (PHASE == 1) ? g_st1 : g_st2;
    atomicAdd(&gst[tid], sh_st[tid]);
}

// ---------------- BN finalize ----------------
template <int PHASE>
__global__ void k_bnfin(const float* __restrict__ gamma,
                        const float* __restrict__ beta, float invN) {
    int i = threadIdx.x;
    const float* st = (PHASE == 1) ? g_st1 : g_st2;
    float mean = st[i] * invN;
    float var = st[i + 128] * invN - mean * mean;
    float s = gamma[i] * rsqrtf(var + BN_EPS);
    if (PHASE == 1) { g_a1[i] = s; g_c1[i] = beta[i] - mean * s; }
    else            { g_a2[i] = s; g_c2[i] = beta[i] - mean * s; }
}

// ---------------- final BN2 + ReLU in place on d_out ----------------
__global__ void k_final(float4* __restrict__ y, int n4) {
    for (int i = blockIdx.x * blockDim.x + threadIdx.x; i < n4;
         i += gridDim.x * blockDim.x) {
        int c4 = i & 31;
        float4 a = __ldg(&((const float4*)g_a2)[c4]);
        float4 b = __ldg(&((const float4*)g_c2)[c4]);
        float4 v = y[i];
        v.x = fmaxf(fmaf(a.x, v.x, b.x), 0.f);
        v.y = fmaxf(fmaf(a.y, v.y, b.y), 0.f);
        v.z = fmaxf(fmaf(a.z, v.z, b.z), 0.f);
        v.w = fmaxf(fmaf(a.w, v.w, b.w), 0.f);
        y[i] = v;
    }
}

// ---------------- launcher ----------------
extern "C" void kernel_launch(void* const* d_in, const int* in_sizes, int n_in,
                              void* d_out, int out_size) {
    const float* x    = (const float*)d_in[0];   // [N,128]
    const int*   ei   = (const int*)  d_in[1];   // [2,E]
    const int*   ew   = (const int*)  d_in[2];   // [E]
    const float* hop  = (const float*)d_in[3];   // [5]
    const float* W1   = (const float*)d_in[4];   // [128,128]
    const float* g1   = (const float*)d_in[6];
    const float* be1  = (const float*)d_in[7];
    const float* W2   = (const float*)d_in[8];
    const float* g2   = (const float*)d_in[10];
    const float* be2  = (const float*)d_in[11];
    float* out = (float*)d_out;

    int n = in_sizes[0] / FDIM;   // 100000
    int E = in_sizes[2];          // 1600000
    int n4 = n * 32;
    float invN = 1.f / (float)n;

    k_prep<<<1, 256>>>(hop);
    k_zero_h<<<2048, 256>>>(n4);
    k_scatter<<<(E + 255) / 256, 256>>>(x, ei, ew, E);   // warp = 32 edges

    int gblocks = (n + 63) / 64;
    k_gemm<1><<<gblocks, 256>>>((const float4*)x, W1, nullptr, n);
    k_bnfin<1><<<1, 128>>>(g1, be1, invN);
    k_gemm<2><<<gblocks, 256>>>(nullptr, W2, out, n);
    k_bnfin<2><<<1, 128>>>(g2, be2, invN);
    k_final<<<2048, 256>>>((float4*)out, n4);
}

// round 10
// speedup vs baseline: 1.0064x; 1.0064x over previous
#include <cuda_runtime.h>

#define FDIM 128
#define KH 5
#define NMAX 100000
#define BN_EPS 1e-5f

typedef unsigned long long u64;

// ---------------- device scratch (static, no allocs) ----------------
__device__ float g_h[(size_t)NMAX * FDIM];   // x + agg  (51.2 MB)
__device__ float g_y[(size_t)NMAX * FDIM];   // y1       (51.2 MB)
__device__ float g_hopw[8];
__device__ float g_st1[256];                 // [0:128) colsum, [128:256) colsumsq
__device__ float g_st2[256];
__device__ float g_a1[FDIM], g_c1[FDIM];     // BN1 fused scale/shift
__device__ float g_a2[FDIM], g_c2[FDIM];     // BN2 fused scale/shift

// ---------------- f32x2 helpers ----------------
__device__ __forceinline__ u64 pk2(float lo, float hi) {
    u64 r;
    asm("mov.b64 %0, {%1, %2};" : "=l"(r) : "f"(lo), "f"(hi));
    return r;
}
__device__ __forceinline__ float2 upk2(u64 v) {
    float2 r;
    asm("mov.b64 {%0, %1}, %2;" : "=f"(r.x), "=f"(r.y) : "l"(v));
    return r;
}
#define FMA2(d, a, b) asm("fma.rn.f32x2 %0, %1, %2, %0;" : "+l"(d) : "l"(a), "l"(b))

// ---------------- softmax + zero stats ----------------
__global__ void k_prep(const float* __restrict__ hop_coef) {
    int t = threadIdx.x;
    if (t < 256) { g_st1[t] = 0.f; g_st2[t] = 0.f; }
    if (t == 0) {
        float v[KH];
        float m = -1e30f;
        for (int i = 0; i < KH; i++) { v[i] = hop_coef[i]; m = fmaxf(m, v[i]); }
        float s = 0.f;
        for (int i = 0; i < KH; i++) { v[i] = expf(v[i] - m); s += v[i]; }
        float inv = 1.f / s;
        for (int i = 0; i < KH; i++) g_hopw[i] = v[i] * inv;
    }
}

// ---------------- init g_h = x (GIN self term; scatter accumulates on top) ----------------
__global__ void k_init(const float4* __restrict__ x, int n4) {
    float4* h4 = (float4*)g_h;
    for (int i = blockIdx.x * blockDim.x + threadIdx.x; i < n4;
         i += gridDim.x * blockDim.x)
        h4[i] = x[i];
}

// ---------------- scatter-add: warp handles 32 edges, meta de-duplicated (R6 winner) ----------------
__global__ void k_scatter(const float* __restrict__ x,
                          const int* __restrict__ ei,
                          const int* __restrict__ ew, int E) {
    int lane = threadIdx.x & 31;
    int warp = (blockIdx.x * blockDim.x + threadIdx.x) >> 5;
    int base = warp * 32;
    if (base >= E) return;

    int e = base + lane;
    u64 mpack = 0;
    float wgt = 0.f;
    if (e < E) {
        int d = ew[e];
        if (d >= 1 && d <= KH) {
            wgt = g_hopw[d - 1];
            int r = ei[e];        // row
            int c = ei[E + e];    // col
            mpack = ((u64)(unsigned)r << 32) | (unsigned)c;
        }
    }

    #pragma unroll 4
    for (int j = 0; j < 32; j++) {
        float w = __shfl_sync(0xffffffffu, wgt, j);
        if (w == 0.f) continue;
        u64 m = __shfl_sync(0xffffffffu, mpack, j);
        int c = (int)(unsigned)m;
        int r = (int)(unsigned)(m >> 32);
        float4 v = ((const float4*)x)[(size_t)c * 32 + lane];
        v.x *= w; v.y *= w; v.z *= w; v.w *= w;
        atomicAdd(((float4*)g_h) + (size_t)r * 32 + lane, v);   // RED.128
    }
}

// ---------------- GEMM + fused BN-stats epilogue (multi-tile, W amortized) ----------------
// PHASE 1: A = g_h (already contains x+agg), Y = g_y, stats -> g_st1
// PHASE 2: A = relu(a1*g_y + c1), Y = OutY, stats -> g_st2
// Grid 391, each block processes tiles t = bid, bid+391, ... (64 rows each).
// Staging map: lane spans 8 rows x 4 col-groups: LDG nL~8, STS 4-way.
// Mainloop (unchanged, proven): broadcast LDS.128 A-pairs + LDS.128 W.
template <int PHASE>
__global__ void __launch_bounds__(256) k_gemm(const float* __restrict__ W,
                                              float* __restrict__ OutY,
                                              int n, int ntiles) {
    const float* A = (PHASE == 1) ? g_h : g_y;
    float* Y       = (PHASE == 1) ? g_y : OutY;

    __shared__ __align__(16) float Ws[FDIM * 128];   // [k][c]  64 KB
    __shared__ __align__(16) float At[FDIM * 64];    // [k][r]  32 KB (transposed)
    __shared__ float sh_st[256];

    int tid = threadIdx.x;
    int tc = tid & 31, tr = tid >> 5;     // mainloop/epilogue coords
    sh_st[tid] = 0.f;

    // stage W once per block (coalesced, row-major [k][c])
    const float4* W4 = (const float4*)W;
    float4* Ws4 = (float4*)Ws;
    #pragma unroll 4
    for (int i = tid; i < FDIM * 32; i += 256) Ws4[i] = W4[i];

    // staging coords: lane spans 8 rows x 4 col-groups; col-group fixed per thread
    int sc4 = (tc & 3) + 4 * tr;          // float4 column group, loop-invariant
    int sr  = tc >> 2;                    // row base 0..7
    float4 a1v, c1v;
    if (PHASE == 2) {
        a1v = __ldg(&((const float4*)g_a1)[sc4]);
        c1v = __ldg(&((const float4*)g_c1)[sc4]);
    }
    const float4* A4 = (const float4*)A;
    int r0 = tr * 8;

    for (int t = blockIdx.x; t < ntiles; t += gridDim.x) {
        int row0 = t * 64;

        // stage A transposed
        #pragma unroll
        for (int j = 0; j < 8; j++) {
            int r = sr + 8 * j;
            int grow = row0 + r;
            float4 v = make_float4(0.f, 0.f, 0.f, 0.f);
            if (grow < n) {
                v = A4[(size_t)grow * 32 + sc4];
                if (PHASE == 2) {
                    v.x = fmaxf(fmaf(a1v.x, v.x, c1v.x), 0.f);
                    v.y = fmaxf(fmaf(a1v.y, v.y, c1v.y), 0.f);
                    v.z = fmaxf(fmaf(a1v.z, v.z, c1v.z), 0.f);
                    v.w = fmaxf(fmaf(a1v.w, v.w, c1v.w), 0.f);
                }
            }
            int k0 = sc4 * 4;
            At[(k0 + 0) * 64 + r] = v.x;
            At[(k0 + 1) * 64 + r] = v.y;
            At[(k0 + 2) * 64 + r] = v.z;
            At[(k0 + 3) * 64 + r] = v.w;
        }
        __syncthreads();

        u64 acc[4][4];
        #pragma unroll
        for (int p = 0; p < 4; p++)
            #pragma unroll
            for (int c = 0; c < 4; c++) acc[p][c] = 0ULL;

        #pragma unroll 4
        for (int k = 0; k < FDIM; k++) {
            float4 wv = Ws4[k * 32 + tc];                 // LDS.128
            u64 w0 = pk2(wv.x, wv.x);
            u64 w1 = pk2(wv.y, wv.y);
            u64 w2 = pk2(wv.z, wv.z);
            u64 w3 = pk2(wv.w, wv.w);
            const ulonglong2* ak = (const ulonglong2*)&At[k * 64 + r0];
            ulonglong2 q01 = ak[0];
            ulonglong2 q23 = ak[1];
            u64 a0 = q01.x, a1 = q01.y, a2 = q23.x, a3 = q23.y;
            FMA2(acc[0][0], a0, w0); FMA2(acc[0][1], a0, w1);
            FMA2(acc[0][2], a0, w2); FMA2(acc[0][3], a0, w3);
            FMA2(acc[1][0], a1, w0); FMA2(acc[1][1], a1, w1);
            FMA2(acc[1][2], a1, w2); FMA2(acc[1][3], a1, w3);
            FMA2(acc[2][0], a2, w0); FMA2(acc[2][1], a2, w1);
            FMA2(acc[2][2], a2, w2); FMA2(acc[2][3], a2, w3);
            FMA2(acc[3][0], a3, w0); FMA2(acc[3][1], a3, w1);
            FMA2(acc[3][2], a3, w2); FMA2(acc[3][3], a3, w3);
        }

        // epilogue: store Y + per-column stats (accumulated in sh_st across tiles)
        float cs[4] = {0.f, 0.f, 0.f, 0.f};
        float cq[4] = {0.f, 0.f, 0.f, 0.f};
        #pragma unroll
        for (int p = 0; p < 4; p++) {
            float2 c0 = upk2(acc[p][0]);
            float2 c1 = upk2(acc[p][1]);
            float2 c2 = upk2(acc[p][2]);
            float2 c3 = upk2(acc[p][3]);
            int r_lo = row0 + r0 + 2 * p;
            int r_hi = r_lo + 1;
            if (r_lo < n) {
                float4 o = make_float4(c0.x, c1.x, c2.x, c3.x);
                ((float4*)Y)[(size_t)r_lo * 32 + tc] = o;
                cs[0] += o.x; cs[1] += o.y; cs[2] += o.z; cs[3] += o.w;
                cq[0] += o.x * o.x; cq[1] += o.y * o.y;
                cq[2] += o.z * o.z; cq[3] += o.w * o.w;
            }
            if (r_hi < n) {
                float4 o = make_float4(c0.y, c1.y, c2.y, c3.y);
                ((float4*)Y)[(size_t)r_hi * 32 + tc] = o;
                cs[0] += o.x; cs[1] += o.y; cs[2] += o.z; cs[3] += o.w;
                cq[0] += o.x * o.x; cq[1] += o.y * o.y;
                cq[2] += o.z * o.z; cq[3] += o.w * o.w;
            }
        }
        #pragma unroll
        for (int c = 0; c < 4; c++) {
            atomicAdd(&sh_st[tc * 4 + c], cs[c]);
            atomicAdd(&sh_st[128 + tc * 4 + c], cq[c]);
        }
        __syncthreads();   // protect At before next tile's staging; sh_st drained
    }

    float* gst = (PHASE == 1) ? g_st1 : g_st2;
    atomicAdd(&gst[tid], sh_st[tid]);
}

// ---------------- BN finalize ----------------
template <int PHASE>
__global__ void k_bnfin(const float* __restrict__ gamma,
                        const float* __restrict__ beta, float invN) {
    int i = threadIdx.x;
    const float* st = (PHASE == 1) ? g_st1 : g_st2;
    float mean = st[i] * invN;
    float var = st[i + 128] * invN - mean * mean;
    float s = gamma[i] * rsqrtf(var + BN_EPS);
    if (PHASE == 1) { g_a1[i] = s; g_c1[i] = beta[i] - mean * s; }
    else            { g_a2[i] = s; g_c2[i] = beta[i] - mean * s; }
}

// ---------------- final BN2 + ReLU in place on d_out ----------------
__global__ void k_final(float4* __restrict__ y, int n4) {
    for (int i = blockIdx.x * blockDim.x + threadIdx.x; i < n4;
         i += gridDim.x * blockDim.x) {
        int c4 = i & 31;
        float4 a = __ldg(&((const float4*)g_a2)[c4]);
        float4 b = __ldg(&((const float4*)g_c2)[c4]);
        float4 v = y[i];
        v.x = fmaxf(fmaf(a.x, v.x, b.x), 0.f);
        v.y = fmaxf(fmaf(a.y, v.y, b.y), 0.f);
        v.z = fmaxf(fmaf(a.z, v.z, b.z), 0.f);
        v.w = fmaxf(fmaf(a.w, v.w, b.w), 0.f);
        y[i] = v;
    }
}

// ---------------- launcher ----------------
extern "C" void kernel_launch(void* const* d_in, const int* in_sizes, int n_in,
                              void* d_out, int out_size) {
    const float* x    = (const float*)d_in[0];   // [N,128]
    const int*   ei   = (const int*)  d_in[1];   // [2,E]
    const int*   ew   = (const int*)  d_in[2];   // [E]
    const float* hop  = (const float*)d_in[3];   // [5]
    const float* W1   = (const float*)d_in[4];   // [128,128]
    const float* g1   = (const float*)d_in[6];
    const float* be1  = (const float*)d_in[7];
    const float* W2   = (const float*)d_in[8];
    const float* g2   = (const float*)d_in[10];
    const float* be2  = (const float*)d_in[11];
    float* out = (float*)d_out;

    int n = in_sizes[0] / FDIM;   // 100000
    int E = in_sizes[2];          // 1600000
    int n4 = n * 32;
    float invN = 1.f / (float)n;

    k_prep<<<1, 256>>>(hop);
    k_init<<<2048, 256>>>((const float4*)x, n4);
    k_scatter<<<(E + 255) / 256, 256>>>(x, ei, ew, E);

    int ntiles = (n + 63) / 64;                  // 1563
    int gblocks = ntiles < 391 ? ntiles : 391;   // ~4 tiles/block
    k_gemm<1><<<gblocks, 256>>>(W1, nullptr, n, ntiles);
    k_bnfin<1><<<1, 128>>>(g1, be1, invN);
    k_gemm<2><<<gblocks, 256>>>(W2, out, n, ntiles);
    k_bnfin<2><<<1, 128>>>(g2, be2, invN);
    k_final<<<2048, 256>>>((float4*)out, n4);
}

// round 11
// speedup vs baseline: 1.1992x; 1.1916x over previous
#include <cuda_runtime.h>

#define FDIM 128
#define KH 5
#define NMAX 100000
#define EMAX 1600000
#define NBMAX 128
#define BN_EPS 1e-5f

typedef unsigned long long u64;

// ---------------- device scratch (static, no allocs) ----------------
__device__ float g_h[(size_t)NMAX * FDIM];   // x + agg  (51.2 MB)
__device__ float g_y[(size_t)NMAX * FDIM];   // y1       (51.2 MB)
__device__ u64   g_epack[EMAX];              // (w_bits<<32)|col per CSR slot
__device__ int   g_cnt[NMAX];                // per-node in-degree
__device__ int   g_rs[NMAX];                 // CSR row start
__device__ int   g_cur[NMAX];                // fill cursor -> row end
__device__ int   g_bsum[NBMAX], g_boff[NBMAX];
__device__ float g_hopw[8];
__device__ float g_st1[256];                 // [0:128) colsum, [128:256) colsumsq
__device__ float g_st2[256];
__device__ float g_a1[FDIM], g_c1[FDIM];     // BN1 fused scale/shift
__device__ float g_a2[FDIM], g_c2[FDIM];     // BN2 fused scale/shift

// ---------------- f32x2 helpers ----------------
__device__ __forceinline__ u64 pk2(float lo, float hi) {
    u64 r;
    asm("mov.b64 %0, {%1, %2};" : "=l"(r) : "f"(lo), "f"(hi));
    return r;
}
__device__ __forceinline__ float2 upk2(u64 v) {
    float2 r;
    asm("mov.b64 {%0, %1}, %2;" : "=f"(r.x), "=f"(r.y) : "l"(v));
    return r;
}
#define FMA2(d, a, b) asm("fma.rn.f32x2 %0, %1, %2, %0;" : "+l"(d) : "l"(a), "l"(b))

// ---------------- prep: zero cnt + zero stats + softmax (one kernel) ----------------
__global__ void k_prep0(const float* __restrict__ hop_coef, int n) {
    int i = blockIdx.x * blockDim.x + threadIdx.x;
    if (i < n) g_cnt[i] = 0;
    if (blockIdx.x == 0) {
        if (threadIdx.x < 256) { g_st1[threadIdx.x] = 0.f; g_st2[threadIdx.x] = 0.f; }
        if (threadIdx.x == 0) {
            float v[KH];
            float m = -1e30f;
            for (int q = 0; q < KH; q++) { v[q] = hop_coef[q]; m = fmaxf(m, v[q]); }
            float s = 0.f;
            for (int q = 0; q < KH; q++) { v[q] = expf(v[q] - m); s += v[q]; }
            float inv = 1.f / s;
            for (int q = 0; q < KH; q++) g_hopw[q] = v[q] * inv;
        }
    }
}

// ---------------- CSR build ----------------
__global__ void k_hist(const int* __restrict__ ei, const int* __restrict__ ew, int E) {
    int e = blockIdx.x * blockDim.x + threadIdx.x;
    if (e >= E) return;
    int d = ew[e];
    if (d < 1 || d > KH) return;
    atomicAdd(&g_cnt[ei[e]], 1);
}

__global__ void k_scan1(int n) {   // 1024 threads/block, Hillis-Steele
    __shared__ int sh[1024];
    int i = blockIdx.x * 1024 + threadIdx.x;
    int v = (i < n) ? g_cnt[i] : 0;
    sh[threadIdx.x] = v;
    __syncthreads();
    for (int off = 1; off < 1024; off <<= 1) {
        int t = (threadIdx.x >= off) ? sh[threadIdx.x - off] : 0;
        __syncthreads();
        sh[threadIdx.x] += t;
        __syncthreads();
    }
    if (i < n) g_rs[i] = sh[threadIdx.x] - v;        // exclusive
    if (threadIdx.x == 1023) g_bsum[blockIdx.x] = sh[1023];
}
__global__ void k_scan2(int nb) {
    if (threadIdx.x == 0) {
        int acc = 0;
        for (int b = 0; b < nb; b++) { g_boff[b] = acc; acc += g_bsum[b]; }
    }
}
__global__ void k_scan3(int n) {
    int i = blockIdx.x * 1024 + threadIdx.x;
    if (i < n) {
        int s = g_rs[i] + g_boff[blockIdx.x];
        g_rs[i] = s;
        g_cur[i] = s;
    }
}

__global__ void k_edges(const int* __restrict__ ei, const int* __restrict__ ew, int E) {
    int e = blockIdx.x * blockDim.x + threadIdx.x;
    if (e >= E) return;
    int d = ew[e];
    if (d < 1 || d > KH) return;
    int r = ei[e];
    int c = ei[E + e];
    float w = g_hopw[d - 1];
    int pos = atomicAdd(&g_cur[r], 1);
    g_epack[pos] = ((u64)__float_as_uint(w) << 32) | (unsigned)c;
}

// ---------------- aggregate: warp per node, h = x[node] + sum(w * x[col]) ----------------
__global__ void k_aggr(const float4* __restrict__ x4, int n) {
    int node = (blockIdx.x * blockDim.x + threadIdx.x) >> 5;
    int lane = threadIdx.x & 31;
    if (node >= n) return;
    int s = g_rs[node], e = g_cur[node];
    float4 acc = __ldg(&x4[(size_t)node * 32 + lane]);
    for (int base = s; base < e; base += 32) {
        int m = min(32, e - base);
        u64 p = (lane < m) ? g_epack[base + lane] : 0ULL;
        #pragma unroll 4
        for (int j = 0; j < 32; j++) {
            if (j >= m) break;
            u64 pj = __shfl_sync(0xffffffffu, p, j);
            int c = (int)(unsigned)pj;
            float w = __uint_as_float((unsigned)(pj >> 32));
            float4 v = __ldg(&x4[(size_t)c * 32 + lane]);
            acc.x = fmaf(w, v.x, acc.x);
            acc.y = fmaf(w, v.y, acc.y);
            acc.z = fmaf(w, v.z, acc.z);
            acc.w = fmaf(w, v.w, acc.w);
        }
    }
    ((float4*)g_h)[(size_t)node * 32 + lane] = acc;
}

// ---------------- GEMM + fused BN-stats epilogue (R10, grid balanced to 296) ----------------
template <int PHASE>
__global__ void __launch_bounds__(256) k_gemm(const float* __restrict__ W,
                                              float* __restrict__ OutY,
                                              int n, int ntiles) {
    const float* A = (PHASE == 1) ? g_h : g_y;
    float* Y       = (PHASE == 1) ? g_y : OutY;

    __shared__ __align__(16) float Ws[FDIM * 128];   // [k][c]  64 KB
    __shared__ __align__(16) float At[FDIM * 64];    // [k][r]  32 KB (transposed)
    __shared__ float sh_st[256];

    int tid = threadIdx.x;
    int tc = tid & 31, tr = tid >> 5;
    sh_st[tid] = 0.f;

    const float4* W4 = (const float4*)W;
    float4* Ws4 = (float4*)Ws;
    #pragma unroll 4
    for (int i = tid; i < FDIM * 32; i += 256) Ws4[i] = W4[i];

    int sc4 = (tc & 3) + 4 * tr;          // float4 column group, loop-invariant
    int sr  = tc >> 2;                    // row base 0..7
    float4 a1v, c1v;
    if (PHASE == 2) {
        a1v = __ldg(&((const float4*)g_a1)[sc4]);
        c1v = __ldg(&((const float4*)g_c1)[sc4]);
    }
    const float4* A4 = (const float4*)A;
    int r0 = tr * 8;

    for (int t = blockIdx.x; t < ntiles; t += gridDim.x) {
        int row0 = t * 64;

        #pragma unroll
        for (int j = 0; j < 8; j++) {
            int r = sr + 8 * j;
            int grow = row0 + r;
            float4 v = make_float4(0.f, 0.f, 0.f, 0.f);
            if (grow < n) {
                v = A4[(size_t)grow * 32 + sc4];
                if (PHASE == 2) {
                    v.x = fmaxf(fmaf(a1v.x, v.x, c1v.x), 0.f);
                    v.y = fmaxf(fmaf(a1v.y, v.y, c1v.y), 0.f);
                    v.z = fmaxf(fmaf(a1v.z, v.z, c1v.z), 0.f);
                    v.w = fmaxf(fmaf(a1v.w, v.w, c1v.w), 0.f);
                }
            }
            int k0 = sc4 * 4;
            At[(k0 + 0) * 64 + r] = v.x;
            At[(k0 + 1) * 64 + r] = v.y;
            At[(k0 + 2) * 64 + r] = v.z;
            At[(k0 + 3) * 64 + r] = v.w;
        }
        __syncthreads();

        u64 acc[4][4];
        #pragma unroll
        for (int p = 0; p < 4; p++)
            #pragma unroll
            for (int c = 0; c < 4; c++) acc[p][c] = 0ULL;

        #pragma unroll 4
        for (int k = 0; k < FDIM; k++) {
            float4 wv = Ws4[k * 32 + tc];
            u64 w0 = pk2(wv.x, wv.x);
            u64 w1 = pk2(wv.y, wv.y);
            u64 w2 = pk2(wv.z, wv.z);
            u64 w3 = pk2(wv.w, wv.w);
            const ulonglong2* ak = (const ulonglong2*)&At[k * 64 + r0];
            ulonglong2 q01 = ak[0];
            ulonglong2 q23 = ak[1];
            u64 a0 = q01.x, a1 = q01.y, a2 = q23.x, a3 = q23.y;
            FMA2(acc[0][0], a0, w0); FMA2(acc[0][1], a0, w1);
            FMA2(acc[0][2], a0, w2); FMA2(acc[0][3], a0, w3);
            FMA2(acc[1][0], a1, w0); FMA2(acc[1][1], a1, w1);
            FMA2(acc[1][2], a1, w2); FMA2(acc[1][3], a1, w3);
            FMA2(acc[2][0], a2, w0); FMA2(acc[2][1], a2, w1);
            FMA2(acc[2][2], a2, w2); FMA2(acc[2][3], a2, w3);
            FMA2(acc[3][0], a3, w0); FMA2(acc[3][1], a3, w1);
            FMA2(acc[3][2], a3, w2); FMA2(acc[3][3], a3, w3);
        }

        float cs[4] = {0.f, 0.f, 0.f, 0.f};
        float cq[4] = {0.f, 0.f, 0.f, 0.f};
        #pragma unroll
        for (int p = 0; p < 4; p++) {
            float2 c0 = upk2(acc[p][0]);
            float2 c1 = upk2(acc[p][1]);
            float2 c2 = upk2(acc[p][2]);
            float2 c3 = upk2(acc[p][3]);
            int r_lo = row0 + r0 + 2 * p;
            int r_hi = r_lo + 1;
            if (r_lo < n) {
                float4 o = make_float4(c0.x, c1.x, c2.x, c3.x);
                ((float4*)Y)[(size_t)r_lo * 32 + tc] = o;
                cs[0] += o.x; cs[1] += o.y; cs[2] += o.z; cs[3] += o.w;
                cq[0] += o.x * o.x; cq[1] += o.y * o.y;
                cq[2] += o.z * o.z; cq[3] += o.w * o.w;
            }
            if (r_hi < n) {
                float4 o = make_float4(c0.y, c1.y, c2.y, c3.y);
                ((float4*)Y)[(size_t)r_hi * 32 + tc] = o;
                cs[0] += o.x; cs[1] += o.y; cs[2] += o.z; cs[3] += o.w;
                cq[0] += o.x * o.x; cq[1] += o.y * o.y;
                cq[2] += o.z * o.z; cq[3] += o.w * o.w;
            }
        }
        #pragma unroll
        for (int c = 0; c < 4; c++) {
            atomicAdd(&sh_st[tc * 4 + c], cs[c]);
            atomicAdd(&sh_st[128 + tc * 4 + c], cq[c]);
        }
        __syncthreads();
    }

    float* gst = (PHASE == 1) ? g_st1 : g_st2;
    atomicAdd(&gst[tid], sh_st[tid]);
}

// ---------------- BN finalize ----------------
template <int PHASE>
__global__ void k_bnfin(const float* __restrict__ gamma,
                        const float* __restrict__ beta, float invN) {
    int i = threadIdx.x;
    const float* st = (PHASE == 1) ? g_st1 : g_st2;
    float mean = st[i] * invN;
    float var = st[i + 128] * invN - mean * mean;
    float s = gamma[i] * rsqrtf(var + BN_EPS);
    if (PHASE == 1) { g_a1[i] = s; g_c1[i] = beta[i] - mean * s; }
    else            { g_a2[i] = s; g_c2[i] = beta[i] - mean * s; }
}

// ---------------- final BN2 + ReLU in place on d_out ----------------
__global__ void k_final(float4* __restrict__ y, int n4) {
    for (int i = blockIdx.x * blockDim.x + threadIdx.x; i < n4;
         i += gridDim.x * blockDim.x) {
        int c4 = i & 31;
        float4 a = __ldg(&((const float4*)g_a2)[c4]);
        float4 b = __ldg(&((const float4*)g_c2)[c4]);
        float4 v = y[i];
        v.x = fmaxf(fmaf(a.x, v.x, b.x), 0.f);
        v.y = fmaxf(fmaf(a.y, v.y, b.y), 0.f);
        v.z = fmaxf(fmaf(a.z, v.z, b.z), 0.f);
        v.w = fmaxf(fmaf(a.w, v.w, b.w), 0.f);
        y[i] = v;
    }
}

// ---------------- launcher ----------------
extern "C" void kernel_launch(void* const* d_in, const int* in_sizes, int n_in,
                              void* d_out, int out_size) {
    const float* x    = (const float*)d_in[0];   // [N,128]
    const int*   ei   = (const int*)  d_in[1];   // [2,E]
    const int*   ew   = (const int*)  d_in[2];   // [E]
    const float* hop  = (const float*)d_in[3];   // [5]
    const float* W1   = (const float*)d_in[4];   // [128,128]
    const float* g1   = (const float*)d_in[6];
    const float* be1  = (const float*)d_in[7];
    const float* W2   = (const float*)d_in[8];
    const float* g2   = (const float*)d_in[10];
    const float* be2  = (const float*)d_in[11];
    float* out = (float*)d_out;

    int n = in_sizes[0] / FDIM;   // 100000
    int E = in_sizes[2];          // 1600000
    int n4 = n * 32;
    float invN = 1.f / (float)n;
    int nb = (n + 1023) / 1024;   // scan blocks (98)

    k_prep0<<<(n + 255) / 256, 256>>>(hop, n);
    k_hist<<<(E + 255) / 256, 256>>>(ei, ew, E);
    k_scan1<<<nb, 1024>>>(n);
    k_scan2<<<1, 32>>>(nb);
    k_scan3<<<nb, 1024>>>(n);
    k_edges<<<(E + 255) / 256, 256>>>(ei, ew, E);
    k_aggr<<<(n * 32 + 255) / 256, 256>>>((const float4*)x, n);

    int ntiles = (n + 63) / 64;                  // 1563
    int gblocks = ntiles < 296 ? ntiles : 296;   // 2 blocks/SM exactly
    k_gemm<1><<<gblocks, 256>>>(W1, nullptr, n, ntiles);
    k_bnfin<1><<<1, 128>>>(g1, be1, invN);
    k_gemm<2><<<gblocks, 256>>>(W2, out, n, ntiles);
    k_bnfin<2><<<1, 128>>>(g2, be2, invN);
    k_final<<<2048, 256>>>((float4*)out, n4);
}

// round 12
// speedup vs baseline: 1.2075x; 1.0070x over previous
#include <cuda_runtime.h>

#define FDIM 128
#define KH 5
#define NMAX 100000
#define EMAX 1600000
#define NBMAX 128
#define BN_EPS 1e-5f

typedef unsigned long long u64;

// ---------------- device scratch (static, no allocs) ----------------
__device__ float g_h[(size_t)NMAX * FDIM];   // x + agg  (51.2 MB)
__device__ float g_y[(size_t)NMAX * FDIM];   // y1       (51.2 MB)
__device__ u64   g_epack[EMAX];              // (w_bits<<32)|col per CSR slot
__device__ int   g_cnt[NMAX];                // per-node in-degree
__device__ int   g_rs[NMAX];                 // CSR row start
__device__ int   g_cur[NMAX];                // fill cursor -> row end
__device__ int   g_bsum[NBMAX], g_boff[NBMAX];
__device__ int   g_ctr[2];                   // GEMM tile-steal counters
__device__ float g_hopw[8];
__device__ float g_st1[256];                 // [0:128) colsum, [128:256) colsumsq
__device__ float g_st2[256];
__device__ float g_a1[FDIM], g_c1[FDIM];     // BN1 fused scale/shift
__device__ float g_a2[FDIM], g_c2[FDIM];     // BN2 fused scale/shift

// ---------------- f32x2 helpers ----------------
__device__ __forceinline__ u64 pk2(float lo, float hi) {
    u64 r;
    asm("mov.b64 %0, {%1, %2};" : "=l"(r) : "f"(lo), "f"(hi));
    return r;
}
__device__ __forceinline__ float2 upk2(u64 v) {
    float2 r;
    asm("mov.b64 {%0, %1}, %2;" : "=f"(r.x), "=f"(r.y) : "l"(v));
    return r;
}
#define FMA2(d, a, b) asm("fma.rn.f32x2 %0, %1, %2, %0;" : "+l"(d) : "l"(a), "l"(b))

// ---------------- prep: zero cnt + stats + counters + softmax ----------------
__global__ void k_prep0(const float* __restrict__ hop_coef, int n) {
    int i = blockIdx.x * blockDim.x + threadIdx.x;
    if (i < n) g_cnt[i] = 0;
    if (blockIdx.x == 0) {
        if (threadIdx.x < 256) { g_st1[threadIdx.x] = 0.f; g_st2[threadIdx.x] = 0.f; }
        if (threadIdx.x == 0) {
            g_ctr[0] = 0;
            g_ctr[1] = 0;
            float v[KH];
            float m = -1e30f;
            for (int q = 0; q < KH; q++) { v[q] = hop_coef[q]; m = fmaxf(m, v[q]); }
            float s = 0.f;
            for (int q = 0; q < KH; q++) { v[q] = expf(v[q] - m); s += v[q]; }
            float inv = 1.f / s;
            for (int q = 0; q < KH; q++) g_hopw[q] = v[q] * inv;
        }
    }
}

// ---------------- CSR build ----------------
__global__ void k_hist(const int* __restrict__ ei, const int* __restrict__ ew, int E) {
    int e = blockIdx.x * blockDim.x + threadIdx.x;
    if (e >= E) return;
    int d = ew[e];
    if (d < 1 || d > KH) return;
    atomicAdd(&g_cnt[ei[e]], 1);
}

__global__ void k_scan1(int n) {   // 1024 threads/block, Hillis-Steele
    __shared__ int sh[1024];
    int i = blockIdx.x * 1024 + threadIdx.x;
    int v = (i < n) ? g_cnt[i] : 0;
    sh[threadIdx.x] = v;
    __syncthreads();
    for (int off = 1; off < 1024; off <<= 1) {
        int t = (threadIdx.x >= off) ? sh[threadIdx.x - off] : 0;
        __syncthreads();
        sh[threadIdx.x] += t;
        __syncthreads();
    }
    if (i < n) g_rs[i] = sh[threadIdx.x] - v;        // exclusive
    if (threadIdx.x == 1023) g_bsum[blockIdx.x] = sh[1023];
}

__global__ void k_scan2(int nb) {  // one block, 128 threads, parallel scan
    __shared__ int sh[NBMAX];
    int t = threadIdx.x;
    int v = (t < nb) ? g_bsum[t] : 0;
    sh[t] = v;
    __syncthreads();
    #pragma unroll
    for (int off = 1; off < NBMAX; off <<= 1) {
        int u = (t >= off) ? sh[t - off] : 0;
        __syncthreads();
        sh[t] += u;
        __syncthreads();
    }
    if (t < nb) g_boff[t] = sh[t] - v;               // exclusive
}

__global__ void k_scan3(int n) {
    int i = blockIdx.x * 1024 + threadIdx.x;
    if (i < n) {
        int s = g_rs[i] + g_boff[blockIdx.x];
        g_rs[i] = s;
        g_cur[i] = s;
    }
}

__global__ void k_edges(const int* __restrict__ ei, const int* __restrict__ ew, int E) {
    int e = blockIdx.x * blockDim.x + threadIdx.x;
    if (e >= E) return;
    int d = ew[e];
    if (d < 1 || d > KH) return;
    int r = ei[e];
    int c = ei[E + e];
    float w = g_hopw[d - 1];
    int pos = atomicAdd(&g_cur[r], 1);
    g_epack[pos] = ((u64)__float_as_uint(w) << 32) | (unsigned)c;
}

// ---------------- aggregate: warp per node, h = x[node] + sum(w * x[col]) ----------------
__global__ void k_aggr(const float4* __restrict__ x4, int n) {
    int node = (blockIdx.x * blockDim.x + threadIdx.x) >> 5;
    int lane = threadIdx.x & 31;
    if (node >= n) return;
    int s = g_rs[node], e = g_cur[node];
    float4 acc = __ldg(&x4[(size_t)node * 32 + lane]);
    for (int base = s; base < e; base += 32) {
        int m = min(32, e - base);
        u64 p = (lane < m) ? g_epack[base + lane] : 0ULL;
        #pragma unroll 4
        for (int j = 0; j < 32; j++) {
            if (j >= m) break;
            u64 pj = __shfl_sync(0xffffffffu, p, j);
            int c = (int)(unsigned)pj;
            float w = __uint_as_float((unsigned)(pj >> 32));
            float4 v = __ldg(&x4[(size_t)c * 32 + lane]);
            acc.x = fmaf(w, v.x, acc.x);
            acc.y = fmaf(w, v.y, acc.y);
            acc.z = fmaf(w, v.z, acc.z);
            acc.w = fmaf(w, v.w, acc.w);
        }
    }
    ((float4*)g_h)[(size_t)node * 32 + lane] = acc;
}

// ---------------- GEMM + fused BN-stats epilogue (dynamic tile stealing) ----------------
template <int PHASE>
__global__ void __launch_bounds__(256) k_gemm(const float* __restrict__ W,
                                              float* __restrict__ OutY,
                                              int n, int ntiles) {
    const float* A = (PHASE == 1) ? g_h : g_y;
    float* Y       = (PHASE == 1) ? g_y : OutY;

    __shared__ __align__(16) float Ws[FDIM * 128];   // [k][c]  64 KB
    __shared__ __align__(16) float At[FDIM * 64];    // [k][r]  32 KB (transposed)
    __shared__ float sh_st[256];
    __shared__ int sh_t;

    int tid = threadIdx.x;
    int tc = tid & 31, tr = tid >> 5;
    sh_st[tid] = 0.f;

    const float4* W4 = (const float4*)W;
    float4* Ws4 = (float4*)Ws;
    #pragma unroll 4
    for (int i = tid; i < FDIM * 32; i += 256) Ws4[i] = W4[i];

    int sc4 = (tc & 3) + 4 * tr;          // float4 column group, loop-invariant
    int sr  = tc >> 2;                    // row base 0..7
    float4 a1v, c1v;
    if (PHASE == 2) {
        a1v = __ldg(&((const float4*)g_a1)[sc4]);
        c1v = __ldg(&((const float4*)g_c1)[sc4]);
    }
    const float4* A4 = (const float4*)A;
    int r0 = tr * 8;

    while (true) {
        if (tid == 0) sh_t = atomicAdd(&g_ctr[PHASE - 1], 1);
        __syncthreads();
        int t = sh_t;
        if (t >= ntiles) break;
        int row0 = t * 64;

        #pragma unroll
        for (int j = 0; j < 8; j++) {
            int r = sr + 8 * j;
            int grow = row0 + r;
            float4 v = make_float4(0.f, 0.f, 0.f, 0.f);
            if (grow < n) {
                v = A4[(size_t)grow * 32 + sc4];
                if (PHASE == 2) {
                    v.x = fmaxf(fmaf(a1v.x, v.x, c1v.x), 0.f);
                    v.y = fmaxf(fmaf(a1v.y, v.y, c1v.y), 0.f);
                    v.z = fmaxf(fmaf(a1v.z, v.z, c1v.z), 0.f);
                    v.w = fmaxf(fmaf(a1v.w, v.w, c1v.w), 0.f);
                }
            }
            int k0 = sc4 * 4;
            At[(k0 + 0) * 64 + r] = v.x;
            At[(k0 + 1) * 64 + r] = v.y;
            At[(k0 + 2) * 64 + r] = v.z;
            At[(k0 + 3) * 64 + r] = v.w;
        }
        __syncthreads();

        u64 acc[4][4];
        #pragma unroll
        for (int p = 0; p < 4; p++)
            #pragma unroll
            for (int c = 0; c < 4; c++) acc[p][c] = 0ULL;

        #pragma unroll 4
        for (int k = 0; k < FDIM; k++) {
            float4 wv = Ws4[k * 32 + tc];
            u64 w0 = pk2(wv.x, wv.x);
            u64 w1 = pk2(wv.y, wv.y);
            u64 w2 = pk2(wv.z, wv.z);
            u64 w3 = pk2(wv.w, wv.w);
            const ulonglong2* ak = (const ulonglong2*)&At[k * 64 + r0];
            ulonglong2 q01 = ak[0];
            ulonglong2 q23 = ak[1];
            u64 a0 = q01.x, a1 = q01.y, a2 = q23.x, a3 = q23.y;
            FMA2(acc[0][0], a0, w0); FMA2(acc[0][1], a0, w1);
            FMA2(acc[0][2], a0, w2); FMA2(acc[0][3], a0, w3);
            FMA2(acc[1][0], a1, w0); FMA2(acc[1][1], a1, w1);
            FMA2(acc[1][2], a1, w2); FMA2(acc[1][3], a1, w3);
            FMA2(acc[2][0], a2, w0); FMA2(acc[2][1], a2, w1);
            FMA2(acc[2][2], a2, w2); FMA2(acc[2][3], a2, w3);
            FMA2(acc[3][0], a3, w0); FMA2(acc[3][1], a3, w1);
            FMA2(acc[3][2], a3, w2); FMA2(acc[3][3], a3, w3);
        }

        float cs[4] = {0.f, 0.f, 0.f, 0.f};
        float cq[4] = {0.f, 0.f, 0.f, 0.f};
        #pragma unroll
        for (int p = 0; p < 4; p++) {
            float2 c0 = upk2(acc[p][0]);
            float2 c1 = upk2(acc[p][1]);
            float2 c2 = upk2(acc[p][2]);
            float2 c3 = upk2(acc[p][3]);
            int r_lo = row0 + r0 + 2 * p;
            int r_hi = r_lo + 1;
            if (r_lo < n) {
                float4 o = make_float4(c0.x, c1.x, c2.x, c3.x);
                ((float4*)Y)[(size_t)r_lo * 32 + tc] = o;
                cs[0] += o.x; cs[1] += o.y; cs[2] += o.z; cs[3] += o.w;
                cq[0] += o.x * o.x; cq[1] += o.y * o.y;
                cq[2] += o.z * o.z; cq[3] += o.w * o.w;
            }
            if (r_hi < n) {
                float4 o = make_float4(c0.y, c1.y, c2.y, c3.y);
                ((float4*)Y)[(size_t)r_hi * 32 + tc] = o;
                cs[0] += o.x; cs[1] += o.y; cs[2] += o.z; cs[3] += o.w;
                cq[0] += o.x * o.x; cq[1] += o.y * o.y;
                cq[2] += o.z * o.z; cq[3] += o.w * o.w;
            }
        }
        #pragma unroll
        for (int c = 0; c < 4; c++) {
            atomicAdd(&sh_st[tc * 4 + c], cs[c]);
            atomicAdd(&sh_st[128 + tc * 4 + c], cq[c]);
        }
        __syncthreads();   // protect At + sh_t before next iteration
    }

    float* gst = (PHASE == 1) ? g_st1 : g_st2;
    atomicAdd(&gst[tid], sh_st[tid]);
}

// ---------------- BN finalize ----------------
template <int PHASE>
__global__ void k_bnfin(const float* __restrict__ gamma,
                        const float* __restrict__ beta, float invN) {
    int i = threadIdx.x;
    const float* st = (PHASE == 1) ? g_st1 : g_st2;
    float mean = st[i] * invN;
    float var = st[i + 128] * invN - mean * mean;
    float s = gamma[i] * rsqrtf(var + BN_EPS);
    if (PHASE == 1) { g_a1[i] = s; g_c1[i] = beta[i] - mean * s; }
    else            { g_a2[i] = s; g_c2[i] = beta[i] - mean * s; }
}

// ---------------- final BN2 + ReLU in place on d_out ----------------
__global__ void k_final(float4* __restrict__ y, int n4) {
    for (int i = blockIdx.x * blockDim.x + threadIdx.x; i < n4;
         i += gridDim.x * blockDim.x) {
        int c4 = i & 31;
        float4 a = __ldg(&((const float4*)g_a2)[c4]);
        float4 b = __ldg(&((const float4*)g_c2)[c4]);
        float4 v = y[i];
        v.x = fmaxf(fmaf(a.x, v.x, b.x), 0.f);
        v.y = fmaxf(fmaf(a.y, v.y, b.y), 0.f);
        v.z = fmaxf(fmaf(a.z, v.z, b.z), 0.f);
        v.w = fmaxf(fmaf(a.w, v.w, b.w), 0.f);
        y[i] = v;
    }
}

// ---------------- launcher ----------------
extern "C" void kernel_launch(void* const* d_in, const int* in_sizes, int n_in,
                              void* d_out, int out_size) {
    const float* x    = (const float*)d_in[0];   // [N,128]
    const int*   ei   = (const int*)  d_in[1];   // [2,E]
    const int*   ew   = (const int*)  d_in[2];   // [E]
    const float* hop  = (const float*)d_in[3];   // [5]
    const float* W1   = (const float*)d_in[4];   // [128,128]
    const float* g1   = (const float*)d_in[6];
    const float* be1  = (const float*)d_in[7];
    const float* W2   = (const float*)d_in[8];
    const float* g2   = (const float*)d_in[10];
    const float* be2  = (const float*)d_in[11];
    float* out = (float*)d_out;

    int n = in_sizes[0] / FDIM;   // 100000
    int E = in_sizes[2];          // 1600000
    int n4 = n * 32;
    float invN = 1.f / (float)n;
    int nb = (n + 1023) / 1024;   // scan blocks (98)

    k_prep0<<<(n + 255) / 256, 256>>>(hop, n);
    k_hist<<<(E + 255) / 256, 256>>>(ei, ew, E);
    k_scan1<<<nb, 1024>>>(n);
    k_scan2<<<1, NBMAX>>>(nb);
    k_scan3<<<nb, 1024>>>(n);
    k_edges<<<(E + 255) / 256, 256>>>(ei, ew, E);
    k_aggr<<<(n * 32 + 255) / 256, 256>>>((const float4*)x, n);

    int ntiles = (n + 63) / 64;                  // 1563
    int gblocks = ntiles < 296 ? ntiles : 296;   // 2 blocks/SM
    k_gemm<1><<<gblocks, 256>>>(W1, nullptr, n, ntiles);
    k_bnfin<1><<<1, 128>>>(g1, be1, invN);
    k_gemm<2><<<gblocks, 256>>>(W2, out, n, ntiles);
    k_bnfin<2><<<1, 128>>>(g2, be2, invN);
    k_final<<<2048, 256>>>((float4*)out, n4);
}